// round 10
// baseline (speedup 1.0000x reference)
#include <cuda_runtime.h>

// Graph TopK pooling — R9 (R7 design + spin-backoff hardening): 6 launches.
//  k_scores   : scores + fused hi16/hi8 histogram + zero tile-states
//  k_select(0): coarse+fine select of hi16 prefix        (~1.3 KB reads)
//  k_hist1    : lo16 histogram of prefix-matching scores + zero hist1/c1
//  k_select(1): final threshold bits
//  k_nodes    : single-pass lookback compaction -> map/poolidx/out_pi + zero hist2/c2
//  k_fused    : edge tiles (flags, pe, scan, compact, attr-copy) + x-gather blocks
// Scratch zero invariant: globals are zero-init at load; each stage zeros what
// the previous stage consumed, so every replay re-establishes the invariant.

#define NMAX 100352
#define EMAX 1600000

__device__ float        g_scores[NMAX];
__device__ unsigned int g_hist1[65536];
__device__ unsigned int g_hist2[65536];
__device__ unsigned int g_c1[256];
__device__ unsigned int g_c2[256];
__device__ int          g_prefix;
__device__ int          g_krem;
__device__ unsigned int g_tbits;
__device__ int          g_map[NMAX];
__device__ int          g_poolidx[NMAX / 2 + 256];
__device__ unsigned int g_ntile[256];   // packed flag<<30 | value
__device__ unsigned int g_etile[512];

// ---------------- scores (warp/node) + fused phase-0 histogram + tile zeroing ----------------
__global__ void k_scores(const float* __restrict__ x, const float* __restrict__ w,
                         const float* __restrict__ b, int N) {
    int bidx = blockIdx.x, t = threadIdx.x;
    if (bidx == 0) {            // zero tile states consumed later this replay
        g_ntile[t] = 0u;
        g_etile[t] = 0u; g_etile[256 + t] = 0u;
    }
    int gtid = bidx * blockDim.x + t;
    int node = gtid >> 5, lane = gtid & 31;
    if (node >= N) return;
    float4 xv = ((const float4*)x)[node * 32 + lane];
    float4 wv = ((const float4*)w)[lane];
    float s = xv.x * wv.x + xv.y * wv.y + xv.z * wv.z + xv.w * wv.w;
#pragma unroll
    for (int o = 16; o > 0; o >>= 1) s += __shfl_down_sync(0xffffffffu, s, o);
    if (lane == 0) {
        float z = s + b[0];
        float sc;
        if (z >= 0.f) sc = 1.f / (1.f + expf(-z));
        else { float e = expf(z); sc = e / (1.f + e); }
        g_scores[node] = sc;
        unsigned int bits = __float_as_uint(sc);  // sc > 0: uint order == float order
        atomicAdd(&g_hist1[bits >> 16], 1u);      // hist1/c1 zeroed by prior replay's k_hist1
        atomicAdd(&g_c1[bits >> 24], 1u);
    }
}

// ---------------- phase-1 histogram (lo16 of prefix matches) + zero hist1/c1 ----------------
__global__ void k_hist1(int N) {
    int idx = blockIdx.x * blockDim.x + threadIdx.x;
    if (idx < 65536) g_hist1[idx] = 0u;           // consumed by select(0) already
    if (idx < 256)   g_c1[idx] = 0u;
    if (idx >= N) return;
    unsigned int bits = __float_as_uint(g_scores[idx]);
    if ((int)(bits >> 16) == g_prefix) {
        atomicAdd(&g_hist2[bits & 0xffffu], 1u);  // hist2/c2 zeroed by prior replay's k_nodes
        atomicAdd(&g_c2[(bits >> 8) & 0xffu], 1u);
    }
}

// find bin containing rank k (ascending): scan 256 coarse, then the winning
// bucket's 256 fine bins. ~1.3 KB of global reads total.
__global__ void k_select(int phase, int k0) {
    __shared__ int sc[256];
    __shared__ int sf2[64];
    __shared__ int s_bucket, s_rem;
    int t = threadIdx.x;
    const unsigned int* __restrict__ C = (phase == 0) ? g_c1 : g_c2;
    const unsigned int* __restrict__ H = (phase == 0) ? g_hist1 : g_hist2;
    int v = (int)C[t];
    sc[t] = v;
    __syncthreads();
    for (int off = 1; off < 256; off <<= 1) {
        int u = (t >= off) ? sc[t - off] : 0;
        __syncthreads();
        sc[t] += u;
        __syncthreads();
    }
    int k = (phase == 0) ? k0 : g_krem;
    int excl = sc[t] - v;
    if (k >= excl && k < excl + v) { s_bucket = t; s_rem = k - excl; }
    __syncthreads();
    int wb = s_bucket;
    uint4 q = make_uint4(0, 0, 0, 0);
    int fv = 0;
    if (t < 64) {
        q = ((const uint4*)H)[wb * 64 + t];
        fv = (int)(q.x + q.y + q.z + q.w);
        sf2[t] = fv;
    }
    __syncthreads();
    for (int off = 1; off < 64; off <<= 1) {
        int u = (t >= off && t < 64) ? sf2[t - off] : 0;
        __syncthreads();
        if (t < 64) sf2[t] += u;
        __syncthreads();
    }
    if (t < 64) {
        int e2 = sf2[t] - fv;
        int rem = s_rem;
        if (rem >= e2 && rem < e2 + fv) {
            int r = rem - e2;
            int bin;
            if (r < (int)q.x)                       { bin = wb * 256 + t * 4 + 0; }
            else { r -= (int)q.x; if (r < (int)q.y) { bin = wb * 256 + t * 4 + 1; }
            else { r -= (int)q.y; if (r < (int)q.z) { bin = wb * 256 + t * 4 + 2; }
            else { r -= (int)q.z;                     bin = wb * 256 + t * 4 + 3; } } }
            if (phase == 0) { g_prefix = bin; g_krem = r; }
            else            { g_tbits = ((unsigned)g_prefix << 16) | (unsigned)bin; }
        }
    }
}

// ---------------- warp-parallel decoupled lookback (warp 0 of each block) ----------------
__device__ __forceinline__ int lookback_excl(unsigned int* tiles, int bid, int cnt, int t) {
    if (t == 0) {
        unsigned int word = (((bid == 0) ? 2u : 1u) << 30) | (unsigned)cnt;
        atomicExch(&tiles[bid], word);
    }
    __syncwarp();
    int excl = 0;
    if (bid > 0) {
        int p = bid - 1;
        bool done = false;
        while (!done) {
            int idx = p - t;
            unsigned int v = 0;
            if (idx >= 0) {
                v = *((volatile unsigned int*)&tiles[idx]);
                while ((v >> 30) == 0u) {
                    __nanosleep(40);
                    v = *((volatile unsigned int*)&tiles[idx]);
                }
            }
            unsigned int fl = (idx >= 0) ? (v >> 30) : 0u;
            unsigned int pm = __ballot_sync(0xffffffffu, fl == 2u);
            int stop_lane = (pm != 0u) ? (__ffs(pm) - 1) : 32;
            int val = (idx >= 0 && t <= stop_lane) ? (int)(v & 0x3fffffffu) : 0;
#pragma unroll
            for (int o = 16; o > 0; o >>= 1) val += __shfl_down_sync(0xffffffffu, val, o);
            if (t == 0) excl += val;
            done = (pm != 0u) || (p - 31 < 0);
            p -= 32;
        }
        if (t == 0) atomicExch(&tiles[bid], (2u << 30) | (unsigned)(excl + cnt));
    }
    return excl;  // meaningful on lane 0
}

// ---------------- single-pass node compaction + zero hist2/c2 ----------------
__global__ void k_nodes(int N, int NK, float* __restrict__ out_pool) {
    __shared__ unsigned char sf[1024];
    __shared__ int ssum[256];
    __shared__ int s_gb;
    int bid = blockIdx.x, t = threadIdx.x;
    int T = gridDim.x * 256, gt = bid * 256 + t;
    for (int i = gt; i < 65536; i += T) g_hist2[i] = 0u;  // consumed by select(1)
    if (gt < 256) g_c2[gt] = 0u;
    int base = bid * 1024;
    unsigned int tb = g_tbits;
    for (int i = t; i < 1024; i += 256) {
        int n = base + i;
        sf[i] = (n < N) ? (unsigned char)(__float_as_uint(g_scores[n]) >= tb) : (unsigned char)0;
    }
    __syncthreads();
    int loc[4];
    int s = 0;
#pragma unroll
    for (int j = 0; j < 4; j++) { loc[j] = s; s += sf[t * 4 + j]; }
    ssum[t] = s;
    __syncthreads();
    for (int off = 1; off < 256; off <<= 1) {
        int u = (t >= off) ? ssum[t - off] : 0;
        __syncthreads();
        ssum[t] += u;
        __syncthreads();
    }
    int cnt = ssum[255];
    if (t < 32) {
        int excl = lookback_excl(g_ntile, bid, cnt, t);
        if (t == 0) s_gb = excl;
    }
    __syncthreads();
    int texcl = ssum[t] - s;
    int gb = s_gb;
#pragma unroll
    for (int j = 0; j < 4; j++) {
        int n = base + t * 4 + j;
        if (n >= N) continue;
        int m = -1;
        if (sf[t * 4 + j]) {
            int r = gb + texcl + loc[j];
            if (r < NK) {  // stable truncation: first NK masked nodes by index
                m = r;
                g_poolidx[r] = n;
                out_pool[r] = (float)n;
            }
        }
        g_map[n] = m;
    }
}

// ---------------- fused: edge tiles (compact + attr copy) and x-gather blocks ----------------
__global__ void k_fused(const int* __restrict__ ei, const float* __restrict__ ea,
                        const float* __restrict__ x, int E, int Ek, int NK, int nbe,
                        float* __restrict__ out_ei, float* __restrict__ out_eo,
                        float* __restrict__ out_pe, float* __restrict__ out_ea,
                        float* __restrict__ outx) {
    __shared__ int s_src[4096];
    __shared__ int s_dst[4096];
    __shared__ short s_list[4096];
    __shared__ unsigned char sf[4096];
    __shared__ int ssum[256];
    __shared__ int s_gb;
    int bid = blockIdx.x, t = threadIdx.x;

    if (bid >= nbe) {  // ---- x-gather blocks (depend only on k_nodes) ----
        int tid = (bid - nbe) * 256 + t;
        if (tid < NK * 32) {
            int r = tid >> 5, c = tid & 31;
            int n = g_poolidx[r];
            ((float4*)outx)[tid] = ((const float4*)x)[n * 32 + c];
        }
        return;
    }

    int base = bid * 4096;
    for (int i = t; i < 4096; i += 256) {
        int e = base + i;
        unsigned char f = 0;
        if (e < E) {
            int sN = ei[e], dN = ei[E + e];
            s_src[i] = sN; s_dst[i] = dN;
            f = (unsigned char)((g_map[sN] >= 0 && g_map[dN] >= 0) ? 1 : 0);
            out_pe[e] = f ? 1.0f : 0.0f;
        }
        sf[i] = f;
    }
    __syncthreads();
    int loc[16];
    int s = 0;
#pragma unroll
    for (int j = 0; j < 16; j++) { loc[j] = s; s += sf[t * 16 + j]; }
    ssum[t] = s;
    __syncthreads();
    for (int off = 1; off < 256; off <<= 1) {
        int u = (t >= off) ? ssum[t - off] : 0;
        __syncthreads();
        ssum[t] += u;
        __syncthreads();
    }
    int cnt = ssum[255];
    if (t < 32) {
        int excl = lookback_excl(g_etile, bid, cnt, t);
        if (t == 0) s_gb = excl;
    }
    __syncthreads();
    int texcl = ssum[t] - s;
    int gb = s_gb;
    for (int j = 0; j < 16; j++) {
        int i = t * 16 + j;
        int e = base + i;
        if (e < E && sf[i]) {
            int lr = texcl + loc[j];       // tile-local rank
            int r = gb + lr;
            s_list[lr] = (short)i;
            int sN = s_src[i], dN = s_dst[i];
            out_ei[r]      = (float)sN;
            out_ei[Ek + r] = (float)dN;
            out_eo[r]      = (float)g_map[sN];
            out_eo[Ek + r] = (float)g_map[dN];
        }
    }
    __syncthreads();
    // attr copy: warp per kept edge row, 32 lanes = 128 B coalesced load+store
    int wid = t >> 5, lane = t & 31;
    for (int j = wid; j < cnt; j += 8) {
        int i = (int)s_list[j];
        size_t e = (size_t)(base + i);
        size_t r = (size_t)(gb + j);
        out_ea[r * 32 + lane] = ea[e * 32 + lane];
    }
}

extern "C" void kernel_launch(void* const* d_in, const int* in_sizes, int n_in,
                              void* d_out, int out_size) {
    const float* x  = (const float*)d_in[0];   // (1, N, 128)
    const float* ea = (const float*)d_in[1];   // (1, E, 32)
    const float* w  = (const float*)d_in[2];   // (1, 128)
    const float* b  = (const float*)d_in[3];   // (1,)
    const int*   ei = (const int*)d_in[4];     // (2, E)

    int N  = in_sizes[0] / 128;
    int E  = in_sizes[4] / 2;
    int NK = N / 2;
    long long Ek_ll = ((long long)out_size - (long long)NK * 129 - (long long)E) / 36;
    int Ek = (int)Ek_ll;

    float* out    = (float*)d_out;
    float* out_x  = out;
    float* out_ei = out_x + (size_t)NK * 128;
    float* out_eo = out_ei + 2 * (size_t)Ek;
    float* out_ea = out_eo + 2 * (size_t)Ek;
    float* out_pi = out_ea + 32 * (size_t)Ek;
    float* out_pe = out_pi + (size_t)NK;

    // 1. scores + fused phase-0 histogram + tile-state zeroing
    k_scores<<<(N * 32 + 255) / 256, 256>>>(x, w, b, N);

    // 2. select hi16 prefix
    k_select<<<1, 256>>>(0, NK - 1);

    // 3. phase-1 histogram (+ zero hist1/c1 for next replay)
    k_hist1<<<(N + 255) / 256, 256>>>(N);

    // 4. final threshold bits
    k_select<<<1, 256>>>(1, 0);

    // 5. node compaction (+ zero hist2/c2 for next replay)
    int nbn = (N + 1023) / 1024;
    k_nodes<<<nbn, 256>>>(N, NK, out_pi);

    // 6. fused edge compaction + attr copy + x-gather
    int nbe = (E + 4095) / 4096;
    int nxg = (NK * 32 + 255) / 256;
    k_fused<<<nbe + nxg, 256>>>(ei, ea, x, E, Ek, NK, nbe,
                                out_ei, out_eo, out_pe, out_ea, out_x);
}